// round 11
// baseline (speedup 1.0000x reference)
#include <cuda_runtime.h>
#include <math.h>

// ---------------------------------------------------------------------------
// Euler_34093450396545, round 10.
// R9 post-mortem: occupancy +17% -> dur FLAT. Real bound: wave quantization —
// 2048 identical CTAs over cap 740/888 both ceil to 3 waves (77% eff).
// Fix: finer work quantum. 12 segments x 18 steps, TPB=384 (12 warps/CTA),
// launch_bounds(384,2) -> 2 CTAs/SM, 24 warps/SM (unchanged), but
// waves = 2048/296 = 6.92 -> 7 x (T/3) = 2.33T vs 3.0T  (-22%).
// smem re-packed to 47.2KB (static 48KB limit): staging CHUNK=6.
// ---------------------------------------------------------------------------

#define NSTEPS  216
#define TPB     384          // 12 warps
#define NSEG    12
#define SEGLEN  18
#define ROWSPB  64           // 2 rows / lane, f32x2 packed
#define CHUNK   6
#define SSTRIDE 68           // staging pitch (floats)

typedef unsigned long long u64;
typedef unsigned int u32;

// ======================= compile-time table ================================
namespace ct {
constexpr double PI = 3.14159265358979323846264338327950288;

constexpr double dsqrt(double x) {
    double y = x > 1.0 ? x : 1.0;
    for (int i = 0; i < 48; ++i) y = 0.5 * (y + x / y);
    return y;
}
constexpr double datan(double t) {
    double s = 1.0;
    for (int i = 0; i < 3; ++i) { t = t / (1.0 + dsqrt(1.0 + t * t)); s *= 2.0; }
    double t2 = t * t, r = 0.0;
    for (int k = 12; k >= 0; --k) r = 1.0 / (2.0 * k + 1.0) - t2 * r;
    return s * t * r;
}
constexpr double datan2(double y, double x) {
    if (x > 0.0) return datan(y / x);
    if (x < 0.0) return (y >= 0.0) ? datan(y / x) + PI : datan(y / x) - PI;
    return (y > 0.0) ? PI / 2 : -PI / 2;
}
constexpr double dsin(double x) {
    double x2 = x * x, term = x, sum = x;
    for (int k = 1; k <= 14; ++k) { term *= -x2 / ((2.0 * k) * (2.0 * k + 1.0)); sum += term; }
    return sum;
}
constexpr float f32(double x) { return (float)x; }

struct CTable { float v[NSTEPS][4]; };   // {th, th, 1024*H*z0, 1024*H*z0}

constexpr CTable make_table() {
    CTable T{};
    const float H     = f32(1.0 / 216.0);
    const float OMEGA = f32(2.0 * PI);
    const float PIH   = f32(0.5 * PI);
    float x = f32(-0.417750770388669);
    float y = f32(-0.9085616622823985);
    for (int n = 0; n < NSTEPS; ++n) {
        float th = f32(datan2((double)y, (double)x));
        float t   = f32((double)n / 216.0);
        float arg = f32((double)PIH * (double)t);
        float s   = f32(dsin((double)arg));
        float z0  = f32((double)f32(0.005) * (double)s);
        float hz  = f32((double)H * (double)z0);
        T.v[n][0] = th; T.v[n][1] = th;
        T.v[n][2] = hz * 1024.0f; T.v[n][3] = hz * 1024.0f;
        float xx = f32((double)x * (double)x);
        float yy = f32((double)y * (double)y);
        float s2 = f32((double)xx + (double)yy);
        float r  = f32(dsqrt((double)s2));
        float al = f32(1.0 - (double)r);
        float ax = f32((double)al * (double)x);
        float oy = f32((double)OMEGA * (double)y);
        float fx = f32((double)ax - (double)oy);
        float ay = f32((double)al * (double)y);
        float ox = f32((double)OMEGA * (double)x);
        float fy = f32((double)ay + (double)ox);
        float hx = f32((double)H * (double)fx);
        float hy = f32((double)H * (double)fy);
        x = f32((double)x + (double)hx);
        y = f32((double)y + (double)hy);
    }
    return T;
}
constexpr CTable h_tbl = make_table();

constexpr float cseg() {                 // (1-H)^SEGLEN
    float omh = f32(1.0 - (double)f32(1.0 / 216.0));
    double p = 1.0;
    for (int i = 0; i < SEGLEN; ++i) p *= (double)omh;
    return (float)p;
}
} // namespace ct

constexpr float CSEG_F = ct::cseg();
constexpr float OMH_F  = 1.0f - 1.0f / 216.0f;
constexpr float HS_F   = 1024.0f / 216.0f;         // 1024*H

__constant__ ct::CTable c_tbl = ct::h_tbl;

// ======================= packed helpers ====================================
static __device__ __forceinline__ u64 pk(float x, float y) {
    u64 r; asm("mov.b64 %0,{%1,%2};" : "=l"(r) : "f"(x), "f"(y)); return r;
}
static __device__ __forceinline__ float2 upk(u64 v) {
    float2 f; asm("mov.b64 {%0,%1},%2;" : "=f"(f.x), "=f"(f.y) : "l"(v)); return f;
}
static __device__ __forceinline__ u64 fadd2(u64 a, u64 b) {
    u64 d; asm("add.rn.f32x2 %0,%1,%2;" : "=l"(d) : "l"(a), "l"(b)); return d;
}
static __device__ __forceinline__ u64 ffma2(u64 a, u64 b, u64 c) {
    u64 d; asm("fma.rn.f32x2 %0,%1,%2,%3;" : "=l"(d) : "l"(a), "l"(b), "l"(c)); return d;
}
static __device__ __forceinline__ u32 f32x2_to_h2(u64 v) {
    u32 h;
    asm("{.reg .b32 lo,hi;\n\t"
        "mov.b64 {lo,hi},%1;\n\t"
        "cvt.rn.f16x2.f32 %0,hi,lo;}\n\t" : "=r"(h) : "l"(v));
    return h;
}
static __device__ __forceinline__ u64 h2_to_f32x2(u32 h) {
    u64 v;
    asm("{.reg .b16 l,h;\n\t"
        ".reg .b32 lo,hi;\n\t"
        "mov.b32 {l,h},%1;\n\t"
        "cvt.f32.f16 lo,l;\n\t"
        "cvt.f32.f16 hi,h;\n\t"
        "mov.b64 %0,{lo,hi};}\n\t" : "=l"(v) : "r"(h));
    return v;
}

static __device__ __forceinline__ u64 gauss_acc(u64 acc, u64 thp, u64 nth0,
                                                u64 kkj, u64 aHj) {
    u64 r;
    asm("{\n\t"
        ".reg .b64 d,q,g;\n\t"
        ".reg .b32 al,ah;\n\t"
        "add.rn.f32x2 d,%1,%2;\n\t"
        "mul.rn.f32x2 q,%3,d;\n\t"
        "mul.rn.f32x2 q,q,d;\n\t"
        "mov.b64 {al,ah},q;\n\t"
        "ex2.approx.ftz.f32 al,al;\n\t"
        "ex2.approx.ftz.f32 ah,ah;\n\t"
        "mov.b64 g,{al,ah};\n\t"
        "mul.rn.f32x2 d,%4,d;\n\t"
        "fma.rn.f32x2 %0,d,g,%5;\n\t"
        "}"
        : "=l"(r) : "l"(thp), "l"(nth0), "l"(kkj), "l"(aHj), "l"(acc));
    return r;
}

static __device__ __forceinline__ u64 forcing(int n, const u64* nth0,
                                              const u64* kk, const u64* aH) {
    float4 e = reinterpret_cast<const float4*>(c_tbl.v)[n];
    u64 thp = pk(e.x, e.y);
    u64 a0  = pk(e.z, e.w);
    u64 a1  = gauss_acc(0ull, thp, nth0[1], kk[1], aH[1]);
    a0 = gauss_acc(a0, thp, nth0[0], kk[0], aH[0]);
    a1 = gauss_acc(a1, thp, nth0[3], kk[3], aH[3]);
    a0 = gauss_acc(a0, thp, nth0[2], kk[2], aH[2]);
    a1 = gauss_acc(a1, thp, nth0[4], kk[4], aH[4]);
    return fadd2(a0, a1);
}

// ======================= main kernel =======================================
// smem (47232 B total, static):
//   [0, 27648)      sF: f16x2 forcing, sF[n*32 + lane]  (also param stage)
//   [27648, 47232)  staging: 12 warps x (CHUNK*SSTRIDE*4 = 1632B)
//                   aliased with exchange: xFseg[12][32] | xmn[12][32] | xmx[12][32]
__global__ void __launch_bounds__(TPB, 2)
euler_kernel(const float* __restrict__ xin, const float* __restrict__ v0,
             float* __restrict__ out) {
    __shared__ __align__(16) unsigned char smem_raw[27648 + NSEG * CHUNK * SSTRIDE * 4];
    u32*   sF     = reinterpret_cast<u32*>(smem_raw);
    float* sStage = reinterpret_cast<float*>(smem_raw + 27648);
    u64*   xFseg  = reinterpret_cast<u64*>(smem_raw + 27648);
    u64*   xmn    = xFseg + NSEG * 32;
    u64*   xmx    = xmn  + NSEG * 32;

    const int tid  = threadIdx.x;
    const int lane = tid & 31;
    const int wid  = tid >> 5;
    const int row0 = blockIdx.x * ROWSPB;

    // coalesced param staging into sF region: 64 rows x 15 f32 = 240 float4
    if (tid < 240) {
        reinterpret_cast<float4*>(sF)[tid] =
            reinterpret_cast<const float4*>(xin + (size_t)row0 * 15)[tid];
    }
    __syncthreads();

    u64 nth0[5], kk[5], aH[5];
    {
        const float* p0 = reinterpret_cast<const float*>(sF) + (2 * lane) * 15;
        const float* p1 = p0 + 15;
        #pragma unroll
        for (int j = 0; j < 5; ++j) {
            float a0 = p0[3 * j], b0 = p0[3 * j + 1], t0 = p0[3 * j + 2];
            float a1 = p1[3 * j], b1 = p1[3 * j + 1], t1 = p1[3 * j + 2];
            nth0[j] = pk(-t0, -t1);
            aH[j]   = pk(-HS_F * a0, -HS_F * a1);
            kk[j]   = pk(-1.4426950408889634f / (2.0f * b0 * b0),
                         -1.4426950408889634f / (2.0f * b1 * b1));
        }
    }
    const u64 OMH2 = pk(OMH_F, OMH_F);

    u64 Z0;   // z scaled by 1024
    {
        float2 vv = reinterpret_cast<const float2*>(v0)[(row0 >> 1) + lane];
        Z0 = pk(vv.x * 1024.0f, vv.y * 1024.0f);
    }
    __syncthreads();    // params consumed; sF free

    const int n0 = wid * SEGLEN;

    // ---- Phase A: forcings for my 18-step segment + segment sum ----------
    u64 Fseg = 0ull;
    #pragma unroll 3
    for (int i = 0; i < SEGLEN; ++i) {
        int n = n0 + i;
        u64 f = forcing(n, nth0, kk, aH);
        sF[n * 32 + lane] = f32x2_to_h2(f);
        Fseg = ffma2(Fseg, OMH2, f);       // = sum c^{SEGLEN-1-i} f_i
    }
    __syncthreads();

    // ---- boundary combine: z at my segment start -------------------------
    xFseg[wid * 32 + lane] = Fseg;
    __syncthreads();
    u64 Zs = Z0;
    {
        const u64 CSEG2 = pk(CSEG_F, CSEG_F);
        #pragma unroll
        for (int u = 0; u < NSEG - 1; ++u)
            if (u < wid) Zs = ffma2(Zs, CSEG2, xFseg[u * 32 + lane]);
    }

    // ---- C1: replay quantized forcings for min/max -----------------------
    float mn0 =  3.402823466e38f, mn1 =  3.402823466e38f;
    float mx0 = -3.402823466e38f, mx1 = -3.402823466e38f;
    {
        u64 Z = Zs;
        #pragma unroll 3
        for (int i = 0; i < SEGLEN; ++i) {
            u64 f = h2_to_f32x2(sF[(n0 + i) * 32 + lane]);
            Z = ffma2(Z, OMH2, f);
            float2 zf = upk(Z);
            mn0 = fminf(mn0, zf.x); mx0 = fmaxf(mx0, zf.x);
            mn1 = fminf(mn1, zf.y); mx1 = fmaxf(mx1, zf.y);
        }
    }
    xmn[wid * 32 + lane] = pk(mn0, mn1);
    xmx[wid * 32 + lane] = pk(mx0, mx1);
    __syncthreads();
    u64 sc, bs;
    {
        #pragma unroll
        for (int u = 0; u < NSEG; ++u) {
            float2 a = upk(xmn[u * 32 + lane]);
            float2 b = upk(xmx[u * 32 + lane]);
            mn0 = fminf(mn0, a.x); mn1 = fminf(mn1, a.y);
            mx0 = fmaxf(mx0, b.x); mx1 = fmaxf(mx1, b.y);
        }
        float s0 = 0.042557f / (mx0 - mn0);
        float s1 = 0.042557f / (mx1 - mn1);
        sc = pk(s0, s1);
        bs = pk(fmaf(-mn0, s0, -0.01563f), fmaf(-mn1, s1, -0.01563f));
    }
    __syncthreads();    // exchange done; staging may overwrite

    // ---- C2: replay + scale + per-warp staged coalesced write ------------
    {
        u64 Z = Zs;
        float* obase  = out + (size_t)row0 * NSTEPS;
        float* stageW = sStage + wid * (CHUNK * SSTRIDE);
        #pragma unroll
        for (int ch = 0; ch < SEGLEN / CHUNK; ++ch) {    // 3 chunks of 6
            #pragma unroll
            for (int c = 0; c < CHUNK; ++c) {
                int n = n0 + ch * CHUNK + c;
                u64 f = h2_to_f32x2(sF[n * 32 + lane]);
                Z = ffma2(Z, OMH2, f);
                u64 o = ffma2(Z, sc, bs);
                *reinterpret_cast<u64*>(&stageW[c * SSTRIDE + 2 * lane]) = o;
            }
            __syncwarp();
            #pragma unroll
            for (int k = 0; k < (ROWSPB * CHUNK) / 32; ++k) {   // 12 iters
                int i = lane + 32 * k;
                int r = i / CHUNK;                       // local row 0..63
                int c = i - r * CHUNK;
                obase[r * NSTEPS + n0 + ch * CHUNK + c] = stageW[c * SSTRIDE + r];
            }
            __syncwarp();
        }
    }
}

// ---------------------------------------------------------------------------
extern "C" void kernel_launch(void* const* d_in, const int* in_sizes, int n_in,
                              void* d_out, int out_size) {
    const float* x  = (const float*)d_in[0];   // (B, 15)
    const float* v0 = (const float*)d_in[1];   // (B,)
    float* out = (float*)d_out;                // (B, 216)

    int B = in_sizes[1];
    int nblocks = B / ROWSPB;                  // 131072 / 64 = 2048

    cudaFuncSetAttribute(euler_kernel,
                         cudaFuncAttributePreferredSharedMemoryCarveout,
                         cudaSharedmemCarveoutMaxShared);
    euler_kernel<<<nblocks, TPB>>>(x, v0, out);
}

// round 13
// speedup vs baseline: 1.3847x; 1.3847x over previous
#include <cuda_runtime.h>
#include <math.h>

// ---------------------------------------------------------------------------
// Euler_34093450396545, round 12.
// R11 build break: min.f32x2 / max.f32x2 DO NOT EXIST in PTX (packed f32x2
// family = add/mul/fma only). Revert min/max to scalar fminf/fmaxf (R8 form;
// the unpack movs are pair-bookkeeping ptxas elides). Keep __fdividef
// (legal, untested): prologue fdiv -> MUFU rcp.
// Net content this round vs best(53.1us): R8 config + __fdividef.
// ---------------------------------------------------------------------------

#define NSTEPS  216
#define TPB     128          // 4 warps
#define NSEG    4
#define SEGLEN  54
#define ROWSPB  64           // 2 rows / lane, f32x2 packed
#define SSTRIDE 68           // staging pitch: =4 mod 32 -> conflict-free

typedef unsigned long long u64;
typedef unsigned int u32;

// ======================= compile-time table ================================
namespace ct {
constexpr double PI = 3.14159265358979323846264338327950288;

constexpr double dsqrt(double x) {
    double y = x > 1.0 ? x : 1.0;
    for (int i = 0; i < 48; ++i) y = 0.5 * (y + x / y);
    return y;
}
constexpr double datan(double t) {
    double s = 1.0;
    for (int i = 0; i < 3; ++i) { t = t / (1.0 + dsqrt(1.0 + t * t)); s *= 2.0; }
    double t2 = t * t, r = 0.0;
    for (int k = 12; k >= 0; --k) r = 1.0 / (2.0 * k + 1.0) - t2 * r;
    return s * t * r;
}
constexpr double datan2(double y, double x) {
    if (x > 0.0) return datan(y / x);
    if (x < 0.0) return (y >= 0.0) ? datan(y / x) + PI : datan(y / x) - PI;
    return (y > 0.0) ? PI / 2 : -PI / 2;
}
constexpr double dsin(double x) {
    double x2 = x * x, term = x, sum = x;
    for (int k = 1; k <= 14; ++k) { term *= -x2 / ((2.0 * k) * (2.0 * k + 1.0)); sum += term; }
    return sum;
}
constexpr float f32(double x) { return (float)x; }

struct CTable { float v[NSTEPS][4]; };   // {th, th, 1024*H*z0, 1024*H*z0}

constexpr CTable make_table() {
    CTable T{};
    const float H     = f32(1.0 / 216.0);
    const float OMEGA = f32(2.0 * PI);
    const float PIH   = f32(0.5 * PI);
    float x = f32(-0.417750770388669);
    float y = f32(-0.9085616622823985);
    for (int n = 0; n < NSTEPS; ++n) {
        float th = f32(datan2((double)y, (double)x));
        float t   = f32((double)n / 216.0);
        float arg = f32((double)PIH * (double)t);
        float s   = f32(dsin((double)arg));
        float z0  = f32((double)f32(0.005) * (double)s);
        float hz  = f32((double)H * (double)z0);
        T.v[n][0] = th; T.v[n][1] = th;
        T.v[n][2] = hz * 1024.0f; T.v[n][3] = hz * 1024.0f;
        float xx = f32((double)x * (double)x);
        float yy = f32((double)y * (double)y);
        float s2 = f32((double)xx + (double)yy);
        float r  = f32(dsqrt((double)s2));
        float al = f32(1.0 - (double)r);
        float ax = f32((double)al * (double)x);
        float oy = f32((double)OMEGA * (double)y);
        float fx = f32((double)ax - (double)oy);
        float ay = f32((double)al * (double)y);
        float ox = f32((double)OMEGA * (double)x);
        float fy = f32((double)ay + (double)ox);
        float hx = f32((double)H * (double)fx);
        float hy = f32((double)H * (double)fy);
        x = f32((double)x + (double)hx);
        y = f32((double)y + (double)hy);
    }
    return T;
}
constexpr CTable h_tbl = make_table();

constexpr float c54() {
    float omh = f32(1.0 - (double)f32(1.0 / 216.0));
    double p = 1.0;
    for (int i = 0; i < SEGLEN; ++i) p *= (double)omh;
    return (float)p;
}
} // namespace ct

constexpr float C54_F = ct::c54();
constexpr float OMH_F = 1.0f - 1.0f / 216.0f;
constexpr float HS_F  = 1024.0f / 216.0f;          // 1024*H

__constant__ ct::CTable c_tbl = ct::h_tbl;

// ======================= packed helpers ====================================
static __device__ __forceinline__ u64 pk(float x, float y) {
    u64 r; asm("mov.b64 %0,{%1,%2};" : "=l"(r) : "f"(x), "f"(y)); return r;
}
static __device__ __forceinline__ float2 upk(u64 v) {
    float2 f; asm("mov.b64 {%0,%1},%2;" : "=f"(f.x), "=f"(f.y) : "l"(v)); return f;
}
static __device__ __forceinline__ u64 fadd2(u64 a, u64 b) {
    u64 d; asm("add.rn.f32x2 %0,%1,%2;" : "=l"(d) : "l"(a), "l"(b)); return d;
}
static __device__ __forceinline__ u64 ffma2(u64 a, u64 b, u64 c) {
    u64 d; asm("fma.rn.f32x2 %0,%1,%2,%3;" : "=l"(d) : "l"(a), "l"(b), "l"(c)); return d;
}
static __device__ __forceinline__ u32 f32x2_to_h2(u64 v) {
    u32 h;
    asm("{.reg .b32 lo,hi;\n\t"
        "mov.b64 {lo,hi},%1;\n\t"
        "cvt.rn.f16x2.f32 %0,hi,lo;}\n\t" : "=r"(h) : "l"(v));
    return h;
}
static __device__ __forceinline__ u64 h2_to_f32x2(u32 h) {
    u64 v;
    asm("{.reg .b16 l,h;\n\t"
        ".reg .b32 lo,hi;\n\t"
        "mov.b32 {l,h},%1;\n\t"
        "cvt.f32.f16 lo,l;\n\t"
        "cvt.f32.f16 hi,h;\n\t"
        "mov.b64 %0,{lo,hi};}\n\t" : "=l"(v) : "r"(h));
    return v;
}

static __device__ __forceinline__ u64 gauss_acc(u64 acc, u64 thp, u64 nth0,
                                                u64 kkj, u64 aHj) {
    u64 r;
    asm("{\n\t"
        ".reg .b64 d,q,g;\n\t"
        ".reg .b32 al,ah;\n\t"
        "add.rn.f32x2 d,%1,%2;\n\t"
        "mul.rn.f32x2 q,%3,d;\n\t"
        "mul.rn.f32x2 q,q,d;\n\t"
        "mov.b64 {al,ah},q;\n\t"
        "ex2.approx.ftz.f32 al,al;\n\t"
        "ex2.approx.ftz.f32 ah,ah;\n\t"
        "mov.b64 g,{al,ah};\n\t"
        "mul.rn.f32x2 d,%4,d;\n\t"
        "fma.rn.f32x2 %0,d,g,%5;\n\t"
        "}"
        : "=l"(r) : "l"(thp), "l"(nth0), "l"(kkj), "l"(aHj), "l"(acc));
    return r;
}

static __device__ __forceinline__ u64 forcing(int n, const u64* nth0,
                                              const u64* kk, const u64* aH) {
    float4 e = reinterpret_cast<const float4*>(c_tbl.v)[n];
    u64 thp = pk(e.x, e.y);
    u64 a0  = pk(e.z, e.w);
    u64 a1  = gauss_acc(0ull, thp, nth0[1], kk[1], aH[1]);
    a0 = gauss_acc(a0, thp, nth0[0], kk[0], aH[0]);
    a1 = gauss_acc(a1, thp, nth0[3], kk[3], aH[3]);
    a0 = gauss_acc(a0, thp, nth0[2], kk[2], aH[2]);
    a1 = gauss_acc(a1, thp, nth0[4], kk[4], aH[4]);
    return fadd2(a0, a1);
}

// ======================= main kernel =======================================
// smem map (bytes):
//   [0, 27648)      sF: f16x2 forcing, sF[n*32 + lane]   (also param stage)
//   [27648, 36352)  staging (4 warps x 2176B) aliased with exchange:
//       xFseg[4][32] u64 | xmn[4][32] u64 | xmx[4][32] u64
__global__ void __launch_bounds__(TPB)
euler_kernel(const float* __restrict__ xin, const float* __restrict__ v0,
             float* __restrict__ out) {
    __shared__ __align__(16) unsigned char smem_raw[36352];
    u32*   sF     = reinterpret_cast<u32*>(smem_raw);
    float* sStage = reinterpret_cast<float*>(smem_raw + 27648);
    u64*   xFseg  = reinterpret_cast<u64*>(smem_raw + 27648);
    u64*   xmn    = xFseg + NSEG * 32;
    u64*   xmx    = xmn  + NSEG * 32;

    const int tid  = threadIdx.x;
    const int lane = tid & 31;
    const int wid  = tid >> 5;
    const int row0 = blockIdx.x * ROWSPB;

    // coalesced param staging into sF region: 64 rows x 15 f32 = 240 float4
    {
        const float4* src = reinterpret_cast<const float4*>(xin + (size_t)row0 * 15);
        float4*       dst = reinterpret_cast<float4*>(sF);
        dst[tid] = src[tid];
        if (tid + TPB < 240) dst[tid + TPB] = src[tid + TPB];
    }
    __syncthreads();

    u64 nth0[5], kk[5], aH[5];
    {
        const float* p0 = reinterpret_cast<const float*>(sF) + (2 * lane) * 15;
        const float* p1 = p0 + 15;
        #pragma unroll
        for (int j = 0; j < 5; ++j) {
            float a0 = p0[3 * j], b0 = p0[3 * j + 1], t0 = p0[3 * j + 2];
            float a1 = p1[3 * j], b1 = p1[3 * j + 1], t1 = p1[3 * j + 2];
            nth0[j] = pk(-t0, -t1);
            aH[j]   = pk(-HS_F * a0, -HS_F * a1);
            kk[j]   = pk(__fdividef(-1.4426950408889634f, 2.0f * b0 * b0),
                         __fdividef(-1.4426950408889634f, 2.0f * b1 * b1));
        }
    }
    const u64 OMH2 = pk(OMH_F, OMH_F);

    u64 Z0;   // z scaled by 1024
    {
        float2 vv = reinterpret_cast<const float2*>(v0)[(row0 >> 1) + lane];
        Z0 = pk(vv.x * 1024.0f, vv.y * 1024.0f);
    }
    __syncthreads();    // params consumed; sF free

    const int n0 = wid * SEGLEN;

    // ---- Phase A: forcings for my 54-step segment + segment sum ----------
    u64 Fseg = 0ull;
    #pragma unroll 3
    for (int i = 0; i < SEGLEN; ++i) {
        int n = n0 + i;
        u64 f = forcing(n, nth0, kk, aH);
        sF[n * 32 + lane] = f32x2_to_h2(f);
        Fseg = ffma2(Fseg, OMH2, f);       // = sum c^{53-i} f_i
    }
    __syncthreads();

    // ---- boundary combine: z at my segment start -------------------------
    xFseg[wid * 32 + lane] = Fseg;
    __syncthreads();
    u64 Zs = Z0;
    {
        const u64 C54 = pk(C54_F, C54_F);
        #pragma unroll
        for (int u = 0; u < NSEG - 1; ++u)
            if (u < wid) Zs = ffma2(Zs, C54, xFseg[u * 32 + lane]);
    }

    // ---- C1: replay quantized forcings for min/max -----------------------
    float mn0 =  3.402823466e38f, mn1 =  3.402823466e38f;
    float mx0 = -3.402823466e38f, mx1 = -3.402823466e38f;
    {
        u64 Z = Zs;
        #pragma unroll 6
        for (int i = 0; i < SEGLEN; ++i) {
            u64 f = h2_to_f32x2(sF[(n0 + i) * 32 + lane]);
            Z = ffma2(Z, OMH2, f);
            float2 zf = upk(Z);
            mn0 = fminf(mn0, zf.x); mx0 = fmaxf(mx0, zf.x);
            mn1 = fminf(mn1, zf.y); mx1 = fmaxf(mx1, zf.y);
        }
    }
    xmn[wid * 32 + lane] = pk(mn0, mn1);
    xmx[wid * 32 + lane] = pk(mx0, mx1);
    __syncthreads();
    u64 sc, bs;
    {
        #pragma unroll
        for (int u = 0; u < NSEG; ++u) {
            float2 a = upk(xmn[u * 32 + lane]);
            float2 b = upk(xmx[u * 32 + lane]);
            mn0 = fminf(mn0, a.x); mn1 = fminf(mn1, a.y);
            mx0 = fmaxf(mx0, b.x); mx1 = fmaxf(mx1, b.y);
        }
        float s0 = __fdividef(0.042557f, mx0 - mn0);
        float s1 = __fdividef(0.042557f, mx1 - mn1);
        sc = pk(s0, s1);
        bs = pk(fmaf(-mn0, s0, -0.01563f), fmaf(-mn1, s1, -0.01563f));
    }
    __syncthreads();    // exchange done; staging may overwrite

    // ---- C2: replay + scale + per-warp staged coalesced write ------------
    {
        u64 Z = Zs;
        float* obase  = out + (size_t)row0 * NSTEPS;
        float* stageW = sStage + wid * (8 * SSTRIDE);
        #pragma unroll
        for (int ch = 0; ch < 7; ++ch) {                 // 6x8 + 1x6 = 54
            const int cl = (ch < 6) ? 8 : 6;
            #pragma unroll
            for (int c = 0; c < 8; ++c) {
                if (c < cl) {
                    int n = n0 + ch * 8 + c;
                    u64 f = h2_to_f32x2(sF[n * 32 + lane]);
                    Z = ffma2(Z, OMH2, f);
                    u64 o = ffma2(Z, sc, bs);
                    *reinterpret_cast<u64*>(&stageW[c * SSTRIDE + 2 * lane]) = o;
                }
            }
            __syncwarp();
            #pragma unroll
            for (int k = 0; k < 16; ++k) {
                int i = lane + 32 * k;
                int r = i >> 3;                          // local row 0..63
                int c = i & 7;
                if (c < cl)
                    obase[r * NSTEPS + n0 + ch * 8 + c] = stageW[c * SSTRIDE + r];
            }
            __syncwarp();
        }
    }
}

// ---------------------------------------------------------------------------
extern "C" void kernel_launch(void* const* d_in, const int* in_sizes, int n_in,
                              void* d_out, int out_size) {
    const float* x  = (const float*)d_in[0];   // (B, 15)
    const float* v0 = (const float*)d_in[1];   // (B,)
    float* out = (float*)d_out;                // (B, 216)

    int B = in_sizes[1];
    int nblocks = B / ROWSPB;                  // 131072 / 64 = 2048

    cudaFuncSetAttribute(euler_kernel,
                         cudaFuncAttributePreferredSharedMemoryCarveout,
                         cudaSharedmemCarveoutMaxShared);
    euler_kernel<<<nblocks, TPB>>>(x, v0, out);
}

// round 14
// speedup vs baseline: 1.4060x; 1.0154x over previous
#include <cuda_runtime.h>
#include <math.h>

// ---------------------------------------------------------------------------
// Euler_34093450396545, round 13.
// R12 post-mortem: 50.7us best; issue 55%, nothing saturated, and R9 proved
// extra warps don't convert -> need ILP per warp. Fix: split each warp's
// 54-step segment into TWO independent 27-step half-chains:
//   Phase A: Fa, Fb accumulated separately; Fseg = c^27*Fa + Fb.
//   C1: chain A from Zs, chain B from Zmid = c^27*Zs + Fa -> serial ffma2
//       depth 54 -> 27, two interleaved LDS/ffma2/minmax streams.
// C2 unchanged (staging layout tied to sequential order). launch_bounds(128,5)
// pins 5 CTAs/SM (regs must stay <= 102 with the extra chain state).
// ---------------------------------------------------------------------------

#define NSTEPS  216
#define TPB     128          // 4 warps
#define NSEG    4
#define SEGLEN  54
#define HALF    27
#define ROWSPB  64           // 2 rows / lane, f32x2 packed
#define SSTRIDE 68           // staging pitch: =4 mod 32 -> conflict-free

typedef unsigned long long u64;
typedef unsigned int u32;

// ======================= compile-time table ================================
namespace ct {
constexpr double PI = 3.14159265358979323846264338327950288;

constexpr double dsqrt(double x) {
    double y = x > 1.0 ? x : 1.0;
    for (int i = 0; i < 48; ++i) y = 0.5 * (y + x / y);
    return y;
}
constexpr double datan(double t) {
    double s = 1.0;
    for (int i = 0; i < 3; ++i) { t = t / (1.0 + dsqrt(1.0 + t * t)); s *= 2.0; }
    double t2 = t * t, r = 0.0;
    for (int k = 12; k >= 0; --k) r = 1.0 / (2.0 * k + 1.0) - t2 * r;
    return s * t * r;
}
constexpr double datan2(double y, double x) {
    if (x > 0.0) return datan(y / x);
    if (x < 0.0) return (y >= 0.0) ? datan(y / x) + PI : datan(y / x) - PI;
    return (y > 0.0) ? PI / 2 : -PI / 2;
}
constexpr double dsin(double x) {
    double x2 = x * x, term = x, sum = x;
    for (int k = 1; k <= 14; ++k) { term *= -x2 / ((2.0 * k) * (2.0 * k + 1.0)); sum += term; }
    return sum;
}
constexpr float f32(double x) { return (float)x; }

struct CTable { float v[NSTEPS][4]; };   // {th, th, 1024*H*z0, 1024*H*z0}

constexpr CTable make_table() {
    CTable T{};
    const float H     = f32(1.0 / 216.0);
    const float OMEGA = f32(2.0 * PI);
    const float PIH   = f32(0.5 * PI);
    float x = f32(-0.417750770388669);
    float y = f32(-0.9085616622823985);
    for (int n = 0; n < NSTEPS; ++n) {
        float th = f32(datan2((double)y, (double)x));
        float t   = f32((double)n / 216.0);
        float arg = f32((double)PIH * (double)t);
        float s   = f32(dsin((double)arg));
        float z0  = f32((double)f32(0.005) * (double)s);
        float hz  = f32((double)H * (double)z0);
        T.v[n][0] = th; T.v[n][1] = th;
        T.v[n][2] = hz * 1024.0f; T.v[n][3] = hz * 1024.0f;
        float xx = f32((double)x * (double)x);
        float yy = f32((double)y * (double)y);
        float s2 = f32((double)xx + (double)yy);
        float r  = f32(dsqrt((double)s2));
        float al = f32(1.0 - (double)r);
        float ax = f32((double)al * (double)x);
        float oy = f32((double)OMEGA * (double)y);
        float fx = f32((double)ax - (double)oy);
        float ay = f32((double)al * (double)y);
        float ox = f32((double)OMEGA * (double)x);
        float fy = f32((double)ay + (double)ox);
        float hx = f32((double)H * (double)fx);
        float hy = f32((double)H * (double)fy);
        x = f32((double)x + (double)hx);
        y = f32((double)y + (double)hy);
    }
    return T;
}
constexpr CTable h_tbl = make_table();

constexpr float cpow(int n) {
    float omh = f32(1.0 - (double)f32(1.0 / 216.0));
    double p = 1.0;
    for (int i = 0; i < n; ++i) p *= (double)omh;
    return (float)p;
}
} // namespace ct

constexpr float C54_F = ct::cpow(SEGLEN);
constexpr float C27_F = ct::cpow(HALF);
constexpr float OMH_F = 1.0f - 1.0f / 216.0f;
constexpr float HS_F  = 1024.0f / 216.0f;          // 1024*H

__constant__ ct::CTable c_tbl = ct::h_tbl;

// ======================= packed helpers ====================================
static __device__ __forceinline__ u64 pk(float x, float y) {
    u64 r; asm("mov.b64 %0,{%1,%2};" : "=l"(r) : "f"(x), "f"(y)); return r;
}
static __device__ __forceinline__ float2 upk(u64 v) {
    float2 f; asm("mov.b64 {%0,%1},%2;" : "=f"(f.x), "=f"(f.y) : "l"(v)); return f;
}
static __device__ __forceinline__ u64 fadd2(u64 a, u64 b) {
    u64 d; asm("add.rn.f32x2 %0,%1,%2;" : "=l"(d) : "l"(a), "l"(b)); return d;
}
static __device__ __forceinline__ u64 ffma2(u64 a, u64 b, u64 c) {
    u64 d; asm("fma.rn.f32x2 %0,%1,%2,%3;" : "=l"(d) : "l"(a), "l"(b), "l"(c)); return d;
}
static __device__ __forceinline__ u32 f32x2_to_h2(u64 v) {
    u32 h;
    asm("{.reg .b32 lo,hi;\n\t"
        "mov.b64 {lo,hi},%1;\n\t"
        "cvt.rn.f16x2.f32 %0,hi,lo;}\n\t" : "=r"(h) : "l"(v));
    return h;
}
static __device__ __forceinline__ u64 h2_to_f32x2(u32 h) {
    u64 v;
    asm("{.reg .b16 l,h;\n\t"
        ".reg .b32 lo,hi;\n\t"
        "mov.b32 {l,h},%1;\n\t"
        "cvt.f32.f16 lo,l;\n\t"
        "cvt.f32.f16 hi,h;\n\t"
        "mov.b64 %0,{lo,hi};}\n\t" : "=l"(v) : "r"(h));
    return v;
}

static __device__ __forceinline__ u64 gauss_acc(u64 acc, u64 thp, u64 nth0,
                                                u64 kkj, u64 aHj) {
    u64 r;
    asm("{\n\t"
        ".reg .b64 d,q,g;\n\t"
        ".reg .b32 al,ah;\n\t"
        "add.rn.f32x2 d,%1,%2;\n\t"
        "mul.rn.f32x2 q,%3,d;\n\t"
        "mul.rn.f32x2 q,q,d;\n\t"
        "mov.b64 {al,ah},q;\n\t"
        "ex2.approx.ftz.f32 al,al;\n\t"
        "ex2.approx.ftz.f32 ah,ah;\n\t"
        "mov.b64 g,{al,ah};\n\t"
        "mul.rn.f32x2 d,%4,d;\n\t"
        "fma.rn.f32x2 %0,d,g,%5;\n\t"
        "}"
        : "=l"(r) : "l"(thp), "l"(nth0), "l"(kkj), "l"(aHj), "l"(acc));
    return r;
}

static __device__ __forceinline__ u64 forcing(int n, const u64* nth0,
                                              const u64* kk, const u64* aH) {
    float4 e = reinterpret_cast<const float4*>(c_tbl.v)[n];
    u64 thp = pk(e.x, e.y);
    u64 a0  = pk(e.z, e.w);
    u64 a1  = gauss_acc(0ull, thp, nth0[1], kk[1], aH[1]);
    a0 = gauss_acc(a0, thp, nth0[0], kk[0], aH[0]);
    a1 = gauss_acc(a1, thp, nth0[3], kk[3], aH[3]);
    a0 = gauss_acc(a0, thp, nth0[2], kk[2], aH[2]);
    a1 = gauss_acc(a1, thp, nth0[4], kk[4], aH[4]);
    return fadd2(a0, a1);
}

// ======================= main kernel =======================================
// smem map (bytes):
//   [0, 27648)      sF: f16x2 forcing, sF[n*32 + lane]   (also param stage)
//   [27648, 36352)  staging (4 warps x 2176B) aliased with exchange:
//       xFseg[4][32] u64 | xmn[4][32] u64 | xmx[4][32] u64
__global__ void __launch_bounds__(TPB, 5)
euler_kernel(const float* __restrict__ xin, const float* __restrict__ v0,
             float* __restrict__ out) {
    __shared__ __align__(16) unsigned char smem_raw[36352];
    u32*   sF     = reinterpret_cast<u32*>(smem_raw);
    float* sStage = reinterpret_cast<float*>(smem_raw + 27648);
    u64*   xFseg  = reinterpret_cast<u64*>(smem_raw + 27648);
    u64*   xmn    = xFseg + NSEG * 32;
    u64*   xmx    = xmn  + NSEG * 32;

    const int tid  = threadIdx.x;
    const int lane = tid & 31;
    const int wid  = tid >> 5;
    const int row0 = blockIdx.x * ROWSPB;

    // coalesced param staging into sF region: 64 rows x 15 f32 = 240 float4
    {
        const float4* src = reinterpret_cast<const float4*>(xin + (size_t)row0 * 15);
        float4*       dst = reinterpret_cast<float4*>(sF);
        dst[tid] = src[tid];
        if (tid + TPB < 240) dst[tid + TPB] = src[tid + TPB];
    }
    __syncthreads();

    u64 nth0[5], kk[5], aH[5];
    {
        const float* p0 = reinterpret_cast<const float*>(sF) + (2 * lane) * 15;
        const float* p1 = p0 + 15;
        #pragma unroll
        for (int j = 0; j < 5; ++j) {
            float a0 = p0[3 * j], b0 = p0[3 * j + 1], t0 = p0[3 * j + 2];
            float a1 = p1[3 * j], b1 = p1[3 * j + 1], t1 = p1[3 * j + 2];
            nth0[j] = pk(-t0, -t1);
            aH[j]   = pk(-HS_F * a0, -HS_F * a1);
            kk[j]   = pk(__fdividef(-1.4426950408889634f, 2.0f * b0 * b0),
                         __fdividef(-1.4426950408889634f, 2.0f * b1 * b1));
        }
    }
    const u64 OMH2 = pk(OMH_F, OMH_F);
    const u64 C27  = pk(C27_F, C27_F);

    u64 Z0;   // z scaled by 1024
    {
        float2 vv = reinterpret_cast<const float2*>(v0)[(row0 >> 1) + lane];
        Z0 = pk(vv.x * 1024.0f, vv.y * 1024.0f);
    }
    __syncthreads();    // params consumed; sF free

    const int n0 = wid * SEGLEN;

    // ---- Phase A: two independent 27-step half-chains --------------------
    u64 Fa = 0ull, Fb = 0ull;
    #pragma unroll 3
    for (int i = 0; i < HALF; ++i) {
        int na = n0 + i, nb = na + HALF;
        u64 fa = forcing(na, nth0, kk, aH);
        sF[na * 32 + lane] = f32x2_to_h2(fa);
        Fa = ffma2(Fa, OMH2, fa);
        u64 fb = forcing(nb, nth0, kk, aH);
        sF[nb * 32 + lane] = f32x2_to_h2(fb);
        Fb = ffma2(Fb, OMH2, fb);
    }
    u64 Fseg = ffma2(Fa, C27, Fb);     // = sum c^{53-i} f_i over the segment
    __syncthreads();

    // ---- boundary combine: z at my segment start -------------------------
    xFseg[wid * 32 + lane] = Fseg;
    __syncthreads();
    u64 Zs = Z0;
    {
        const u64 C54 = pk(C54_F, C54_F);
        #pragma unroll
        for (int u = 0; u < NSEG - 1; ++u)
            if (u < wid) Zs = ffma2(Zs, C54, xFseg[u * 32 + lane]);
    }
    u64 Zmid = ffma2(Zs, C27, Fa);     // z entering second half-chain

    // ---- C1: dual-chain replay for min/max -------------------------------
    float mn0 =  3.402823466e38f, mn1 =  3.402823466e38f;
    float mx0 = -3.402823466e38f, mx1 = -3.402823466e38f;
    {
        u64 Za = Zs, Zb = Zmid;
        #pragma unroll 3
        for (int i = 0; i < HALF; ++i) {
            u64 fa = h2_to_f32x2(sF[(n0 + i) * 32 + lane]);
            Za = ffma2(Za, OMH2, fa);
            u64 fb = h2_to_f32x2(sF[(n0 + HALF + i) * 32 + lane]);
            Zb = ffma2(Zb, OMH2, fb);
            float2 za = upk(Za), zb = upk(Zb);
            mn0 = fminf(mn0, za.x); mx0 = fmaxf(mx0, za.x);
            mn1 = fminf(mn1, za.y); mx1 = fmaxf(mx1, za.y);
            mn0 = fminf(mn0, zb.x); mx0 = fmaxf(mx0, zb.x);
            mn1 = fminf(mn1, zb.y); mx1 = fmaxf(mx1, zb.y);
        }
    }
    xmn[wid * 32 + lane] = pk(mn0, mn1);
    xmx[wid * 32 + lane] = pk(mx0, mx1);
    __syncthreads();
    u64 sc, bs;
    {
        #pragma unroll
        for (int u = 0; u < NSEG; ++u) {
            float2 a = upk(xmn[u * 32 + lane]);
            float2 b = upk(xmx[u * 32 + lane]);
            mn0 = fminf(mn0, a.x); mn1 = fminf(mn1, a.y);
            mx0 = fmaxf(mx0, b.x); mx1 = fmaxf(mx1, b.y);
        }
        float s0 = __fdividef(0.042557f, mx0 - mn0);
        float s1 = __fdividef(0.042557f, mx1 - mn1);
        sc = pk(s0, s1);
        bs = pk(fmaf(-mn0, s0, -0.01563f), fmaf(-mn1, s1, -0.01563f));
    }
    __syncthreads();    // exchange done; staging may overwrite

    // ---- C2: sequential replay + scale + staged coalesced write ----------
    {
        u64 Z = Zs;
        float* obase  = out + (size_t)row0 * NSTEPS;
        float* stageW = sStage + wid * (8 * SSTRIDE);
        #pragma unroll
        for (int ch = 0; ch < 7; ++ch) {                 // 6x8 + 1x6 = 54
            const int cl = (ch < 6) ? 8 : 6;
            #pragma unroll
            for (int c = 0; c < 8; ++c) {
                if (c < cl) {
                    int n = n0 + ch * 8 + c;
                    u64 f = h2_to_f32x2(sF[n * 32 + lane]);
                    Z = ffma2(Z, OMH2, f);
                    u64 o = ffma2(Z, sc, bs);
                    *reinterpret_cast<u64*>(&stageW[c * SSTRIDE + 2 * lane]) = o;
                }
            }
            __syncwarp();
            #pragma unroll
            for (int k = 0; k < 16; ++k) {
                int i = lane + 32 * k;
                int r = i >> 3;                          // local row 0..63
                int c = i & 7;
                if (c < cl)
                    obase[r * NSTEPS + n0 + ch * 8 + c] = stageW[c * SSTRIDE + r];
            }
            __syncwarp();
        }
    }
}

// ---------------------------------------------------------------------------
extern "C" void kernel_launch(void* const* d_in, const int* in_sizes, int n_in,
                              void* d_out, int out_size) {
    const float* x  = (const float*)d_in[0];   // (B, 15)
    const float* v0 = (const float*)d_in[1];   // (B,)
    float* out = (float*)d_out;                // (B, 216)

    int B = in_sizes[1];
    int nblocks = B / ROWSPB;                  // 131072 / 64 = 2048

    cudaFuncSetAttribute(euler_kernel,
                         cudaFuncAttributePreferredSharedMemoryCarveout,
                         cudaSharedmemCarveoutMaxShared);
    euler_kernel<<<nblocks, TPB>>>(x, v0, out);
}